// round 11
// baseline (speedup 1.0000x reference)
#include <cuda_runtime.h>
#include <math.h>

#define NG 1708
#define NGV 427           // NG/4 exactly
#define NH 5
#define NB 16
#define NC 34
#define NM 128            // interpolation nodes per (b,h)
#define NSPLIT 8          // blocks per (b,h) in table stage
#define NODES_PB (NM / NSPLIT)    // 16 nodes per block
#define THR_PN 16                 // threads per node
#define SEG 107                   // ceil(NG/16); last thread gets 103
#define TPB 256

#define LOG2E 1.44269504088896340736f

// Scratch (no allocations allowed)
__device__ float g_h[NB * NG];                  // hidden state per layer
__device__ float g_k[NH * NB * NG];             // centered k (kt = k - c)
__device__ float g_v[NH * NB * NG];             // v
__device__ float g_a[NB * NG];                  // head-summed attention out
__device__ float g_FR[NH * NB * NM * 2];        // (F=log2 f, R=g/f) interleaved
__device__ float g_prm[NH * NB * 4];            // q2min, dq, invdq, halfr
__device__ float g_stats[NB * 2];               // (sum a, sum a^2) atomics

__device__ __forceinline__ float ex2(float a) {
    float r; asm("ex2.approx.f32 %0, %1;" : "=f"(r) : "f"(a)); return r;
}
__device__ __forceinline__ float lg2(float a) {
    float r; asm("lg2.approx.f32 %0, %1;" : "=f"(r) : "f"(a)); return r;
}

// ---------------------------------------------------------------------------
// prep: per (b,h). For L>0 applies previous layer's LN+residual (stats come
// precomputed from interp2 atomics). Computes kt=k-c (c=midrange, exactly
// softmax-invariant), v, and node-grid params.  grid (NH, NB), 256 thr.
// ---------------------------------------------------------------------------
__global__ __launch_bounds__(TPB) void prep_kernel(
    const float* __restrict__ x, int first,
    const float* __restrict__ WQ, const float* __restrict__ WK,
    const float* __restrict__ WV,
    const float* __restrict__ ln_a, const float* __restrict__ ln_b)
{
    __shared__ float sk[NG];
    __shared__ float sv[NG];
    __shared__ float sred[32];
    const int h = blockIdx.x, b = blockIdx.y;
    const int idx = h * NB + b;
    const int tid = threadIdx.x;
    const float* __restrict__ wq = WQ + h * NG;
    const float* __restrict__ wk = WK + h * NG;
    const float* __restrict__ wv = WV + h * NG;

    float mean = 0.f, inv = 0.f;
    if (!first) {
        float S = g_stats[b * 2], SS = g_stats[b * 2 + 1];
        mean = S / (float)NG;
        float var = (SS - (float)NG * mean * mean) / (float)(NG - 1);
        var = fmaxf(var, 0.f);
        inv = 1.f / (sqrtf(var) + 1e-6f);
    }

    float kmax = -3.4e38f, kmin = 3.4e38f, qmax = -3.4e38f, qmin = 3.4e38f;
    for (int j = tid; j < NG; j += TPB) {
        float hv;
        if (first) {
            hv = x[b * NG + j];
        } else {
            float a = g_a[b * NG + j];
            hv = g_h[b * NG + j]
               + fmaf(ln_a[j] * (a - mean), inv, ln_b[j]);
        }
        if (h == 0) sv[j] = hv;            // stage for g_h writeback
        float k = hv * wk[j];
        float v = hv * wv[j];
        float q = hv * wq[j] * LOG2E;
        sk[j] = k;
        g_v[idx * NG + j] = v;
        kmax = fmaxf(kmax, k); kmin = fminf(kmin, k);
        qmax = fmaxf(qmax, q); qmin = fminf(qmin, q);
    }
    #pragma unroll
    for (int o = 16; o; o >>= 1) {
        kmax = fmaxf(kmax, __shfl_xor_sync(0xffffffffu, kmax, o));
        kmin = fminf(kmin, __shfl_xor_sync(0xffffffffu, kmin, o));
        qmax = fmaxf(qmax, __shfl_xor_sync(0xffffffffu, qmax, o));
        qmin = fminf(qmin, __shfl_xor_sync(0xffffffffu, qmin, o));
    }
    const int w = tid >> 5;
    if ((tid & 31) == 0) {
        sred[w] = kmax; sred[8 + w] = kmin;
        sred[16 + w] = qmax; sred[24 + w] = qmin;
    }
    __syncthreads();
    __shared__ float sp[2];   // c, (unused)
    if (tid == 0) {
        float KM = sred[0], Km = sred[8], QM = sred[16], Qm = sred[24];
        #pragma unroll
        for (int i = 1; i < 8; i++) {
            KM = fmaxf(KM, sred[i]);      Km = fminf(Km, sred[8 + i]);
            QM = fmaxf(QM, sred[16 + i]); Qm = fminf(Qm, sred[24 + i]);
        }
        float c = 0.5f * (KM + Km);
        float halfr = 0.5f * (KM - Km);
        float dq = fmaxf((QM - Qm) / (float)(NM - 1), 1e-12f);
        g_prm[idx * 4 + 0] = Qm;
        g_prm[idx * 4 + 1] = dq;
        g_prm[idx * 4 + 2] = 1.f / dq;
        g_prm[idx * 4 + 3] = halfr;
        sp[0] = c;
    }
    __syncthreads();
    const float c = sp[0];
    for (int j = tid; j < NG; j += TPB) {
        g_k[idx * NG + j] = sk[j] - c;
        if (h == 0) g_h[b * NG + j] = sv[j];   // hidden state for this layer
    }
}

// ---------------------------------------------------------------------------
// table: per (b,h) sample F(q)=log2 sum_j 2^{q*kt_j}, R(q)=sum e*v/f at NM
// nodes. kt pre-centered; per-node shift s=|t|*halfr makes all args <= 0.
// grid (NSPLIT, NH, NB); 256 thr = 16 nodes x 16 threads.
// ---------------------------------------------------------------------------
__global__ __launch_bounds__(TPB) void table_kernel()
{
    __shared__ __align__(16) float sk[NG];
    __shared__ __align__(16) float sv[NG];
    const int chunk = blockIdx.x, h = blockIdx.y, b = blockIdx.z;
    const int idx = h * NB + b;
    const int tid = threadIdx.x;

    if (chunk == 0 && h == 0 && tid == 0) {       // zero LN stats (pre-interp2)
        g_stats[b * 2] = 0.f;
        g_stats[b * 2 + 1] = 0.f;
    }

    // vectorized smem fill from hot L2
    const float4* __restrict__ gk4 = reinterpret_cast<const float4*>(g_k + idx * NG);
    const float4* __restrict__ gv4 = reinterpret_cast<const float4*>(g_v + idx * NG);
    float4* __restrict__ sk4 = reinterpret_cast<float4*>(sk);
    float4* __restrict__ sv4 = reinterpret_cast<float4*>(sv);
    for (int j = tid; j < NGV; j += TPB) {
        sk4[j] = gk4[j];
        sv4[j] = gv4[j];
    }
    const float q2min = g_prm[idx * 4 + 0];
    const float dq    = g_prm[idx * 4 + 1];
    const float halfr = g_prm[idx * 4 + 3];
    __syncthreads();

    const int m = chunk * NODES_PB + (tid >> 4);
    const int rr = tid & (THR_PN - 1);
    const float t = q2min + (float)m * dq;
    const float s = fabsf(t) * halfr;          // >= t*kt_j for all j
    float f = 0.f, g = 0.f;
    const int j0 = rr * SEG;
    const int j1 = min(j0 + SEG, NG);
    #pragma unroll 4
    for (int j = j0; j < j1; j++) {
        float e = ex2(fmaf(t, sk[j], -s));
        f += e;
        g = fmaf(e, sv[j], g);
    }
    #pragma unroll
    for (int o = 1; o < THR_PN; o <<= 1) {
        f += __shfl_xor_sync(0xffffffffu, f, o);
        g += __shfl_xor_sync(0xffffffffu, g, o);
    }
    if (rr == 0) {
        g_FR[(idx * NM + m) * 2]     = s + lg2(f);
        g_FR[(idx * NM + m) * 2 + 1] = g / f;
    }
}

// ---------------------------------------------------------------------------
// interp2: per row i, all NH heads: cubic-interp F,R; exact diagonal term;
// head-sum a_i -> g_a. Block-reduces sum/sumsq -> atomics for LN stats.
// grid (7, NB), 256 thr.
// ---------------------------------------------------------------------------
__global__ __launch_bounds__(TPB) void interp2_kernel(
    const float* __restrict__ WQ, const float* __restrict__ W0)
{
    __shared__ float sred[16];
    const int b = blockIdx.y;
    const int i = blockIdx.x * TPB + threadIdx.x;
    const int tid = threadIdx.x;
    const bool ok = (i < NG);

    float a = 0.f;
    if (ok) {
        const float hv = g_h[b * NG + i];
        #pragma unroll
        for (int h = 0; h < NH; h++) {
            const int idx = h * NB + b;
            const float q2 = hv * WQ[h * NG + i] * LOG2E;
            const float kt = g_k[idx * NG + i];
            const float v  = g_v[idx * NG + i];
            const float q2min = g_prm[idx * 4 + 0];
            const float invdq = g_prm[idx * 4 + 2];

            float u = (q2 - q2min) * invdq;
            int j0 = (int)floorf(u);
            j0 = min(max(j0, 1), NM - 3);
            float ww = u - (float)j0;
            float aa = ww + 1.f, bb = ww - 1.f, cc = ww - 2.f;
            float wm1 = -ww * bb * cc * (1.f / 6.f);
            float w0  = aa * bb * cc * 0.5f;
            float w1  = -aa * ww * cc * 0.5f;
            float w2  = aa * ww * bb * (1.f / 6.f);

            const float2* __restrict__ FRp =
                reinterpret_cast<const float2*>(g_FR) + idx * NM + (j0 - 1);
            float2 p0 = FRp[0], p1 = FRp[1], p2 = FRp[2], p3 = FRp[3];
            float F = wm1 * p0.x + w0 * p1.x + w1 * p2.x + w2 * p3.x;
            float R = wm1 * p0.y + w0 * p1.y + w1 * p2.y + w2 * p3.y;

            float ed = ex2(fmaf(q2, kt, -F));   // e_i / f
            a = fmaf(W0[h], R - ed * v, a);
        }
        g_a[b * NG + i] = a;
    }

    // block-reduce sum, sumsq -> atomics
    float s = ok ? a : 0.f;
    float ss = ok ? a * a : 0.f;
    #pragma unroll
    for (int o = 16; o; o >>= 1) {
        s  += __shfl_xor_sync(0xffffffffu, s,  o);
        ss += __shfl_xor_sync(0xffffffffu, ss, o);
    }
    const int w = tid >> 5;
    if ((tid & 31) == 0) { sred[w] = s; sred[8 + w] = ss; }
    __syncthreads();
    if (tid == 0) {
        float S = 0.f, SS = 0.f;
        #pragma unroll
        for (int k = 0; k < 8; k++) { S += sred[k]; SS += sred[8 + k]; }
        atomicAdd(&g_stats[b * 2], S);
        atomicAdd(&g_stats[b * 2 + 1], SS);
    }
}

// ---------------------------------------------------------------------------
// final: apply layer-3 LN+residual (stats precomputed), FC, log_softmax.
// grid NB, 1024 thr.
// ---------------------------------------------------------------------------
__global__ __launch_bounds__(1024) void final_kernel(
    const float* __restrict__ ln_a, const float* __restrict__ ln_b,
    const float* __restrict__ fc_w, const float* __restrict__ fc_b,
    float* __restrict__ out)
{
    __shared__ float4 sa4[NGV];
    __shared__ float slog[NC];
    __shared__ float s_ls;
    const int b = blockIdx.x, tid = threadIdx.x;
    const int w = tid >> 5, l = tid & 31;

    float S = g_stats[b * 2], SS = g_stats[b * 2 + 1];
    float mean = S / (float)NG;
    float var = (SS - (float)NG * mean * mean) / (float)(NG - 1);
    var = fmaxf(var, 0.f);
    float inv = 1.f / (sqrtf(var) + 1e-6f);

    if (tid < NGV) {
        float4 a  = reinterpret_cast<const float4*>(g_a + b * NG)[tid];
        float4 bs = reinterpret_cast<const float4*>(g_h + b * NG)[tid];
        float4 la = reinterpret_cast<const float4*>(ln_a)[tid];
        float4 lb = reinterpret_cast<const float4*>(ln_b)[tid];
        float4 o;
        o.x = bs.x + fmaf(la.x * (a.x - mean), inv, lb.x);
        o.y = bs.y + fmaf(la.y * (a.y - mean), inv, lb.y);
        o.z = bs.z + fmaf(la.z * (a.z - mean), inv, lb.z);
        o.w = bs.w + fmaf(la.w * (a.w - mean), inv, lb.w);
        sa4[tid] = o;
    }
    __syncthreads();

    for (int c = w; c < NC; c += 32) {
        const float4* __restrict__ wr =
            reinterpret_cast<const float4*>(fc_w + c * NG);
        float d = 0.f;
        for (int j = l; j < NGV; j += 32) {
            float4 a = sa4[j], q = wr[j];
            d = fmaf(a.x, q.x, d); d = fmaf(a.y, q.y, d);
            d = fmaf(a.z, q.z, d); d = fmaf(a.w, q.w, d);
        }
        #pragma unroll
        for (int o = 16; o; o >>= 1) d += __shfl_xor_sync(0xffffffffu, d, o);
        if (l == 0) slog[c] = d + fc_b[c];
    }
    __syncthreads();
    if (tid == 0) {
        float M = slog[0];
        #pragma unroll
        for (int c = 1; c < NC; c++) M = fmaxf(M, slog[c]);
        float sum = 0.f;
        for (int c = 0; c < NC; c++) sum += expf(slog[c] - M);
        s_ls = M + logf(sum);
    }
    __syncthreads();
    if (tid < NC) out[b * NC + tid] = slog[tid] - s_ls;
}

extern "C" void kernel_launch(void* const* d_in, const int* in_sizes, int n_in,
                              void* d_out, int out_size) {
    const float* x    = (const float*)d_in[0];
    const float* WQ[3] = {(const float*)d_in[1], (const float*)d_in[5], (const float*)d_in[9]};
    const float* WK[3] = {(const float*)d_in[2], (const float*)d_in[6], (const float*)d_in[10]};
    const float* WV[3] = {(const float*)d_in[3], (const float*)d_in[7], (const float*)d_in[11]};
    const float* W0[3] = {(const float*)d_in[4], (const float*)d_in[8], (const float*)d_in[12]};
    const float* ln_a = (const float*)d_in[13];
    const float* ln_b = (const float*)d_in[14];
    const float* fc_w = (const float*)d_in[15];
    const float* fc_b = (const float*)d_in[16];

    for (int L = 0; L < 3; L++) {
        prep_kernel<<<dim3(NH, NB), TPB>>>(x, L == 0 ? 1 : 0,
                                           WQ[L], WK[L], WV[L], ln_a, ln_b);
        table_kernel<<<dim3(NSPLIT, NH, NB), TPB>>>();
        interp2_kernel<<<dim3(7, NB), TPB>>>(WQ[L], W0[L]);
    }
    final_kernel<<<NB, 1024>>>(ln_a, ln_b, fc_w, fc_b, (float*)d_out);
}